// round 2
// baseline (speedup 1.0000x reference)
#include <cuda_runtime.h>
#include <cuda_bf16.h>
#include <math_constants.h>

// Problem constants
#define B_   16
#define N_   3136
#define C_   512
#define H_   8
#define D_   64
#define HH_  56
#define AG_  144
#define PS_  12
#define SCALE_ 0.125f   // 64^-0.5

// Scratch (device globals; allocation-free rule)
__device__ float g_qkv[(size_t)B_ * N_ * 3 * C_];        // (b, n, 3c) 308MB
__device__ float g_agent[(size_t)B_ * AG_ * C_];          // (b, 144, c)
__device__ float g_s1[(size_t)B_ * H_ * AG_ * N_];        // (bh, 144, n) 231MB
__device__ float g_av[(size_t)B_ * H_ * AG_ * D_];        // (bh, 144, 64)
__device__ float g_attn[(size_t)B_ * N_ * C_];            // (b, n, c) 103MB

// ---------------------------------------------------------------------------
// Generic tiled SGEMM: C = alpha * A @ op(B) (+ bias)
// A: row-major M x K (lda). TRANS_B: B row-major N x K (ldb) -> A@B^T
//                          !TRANS_B: B row-major K x N (ldb) -> A@B
// Batched: batch = blockIdx.z, decomposed as (outer=batch>>3, inner=batch&7).
// ---------------------------------------------------------------------------
#define BM 128
#define BN 128
#define BK 8

template <bool TRANS_B>
__global__ __launch_bounds__(256) void sgemm_kernel(
    const float* __restrict__ A, const float* __restrict__ B,
    float* __restrict__ C,
    int M, int N, int K, int lda, int ldb, int ldc,
    long sA_o, long sA_i, long sB_o, long sB_i, long sC_o, long sC_i,
    float alpha, const float* __restrict__ bias)
{
    int batch = blockIdx.z;
    int bo = batch >> 3, bi = batch & 7;
    A += bo * sA_o + bi * sA_i;
    B += bo * sB_o + bi * sB_i;
    C += bo * sC_o + bi * sC_i;

    int m0 = blockIdx.y * BM;
    int n0 = blockIdx.x * BN;

    __shared__ float As[BK][BM];
    __shared__ float Bs[BK][BN];

    int tid = threadIdx.x;
    int ty = tid >> 4, tx = tid & 15;

    float acc[8][8];
#pragma unroll
    for (int i = 0; i < 8; i++)
#pragma unroll
        for (int j = 0; j < 8; j++) acc[i][j] = 0.f;

    for (int k0 = 0; k0 < K; k0 += BK) {
        // Load A tile (BM x BK)
#pragma unroll
        for (int it = 0; it < (BM * BK) / 256; it++) {
            int i = tid + it * 256;
            int m = i / BK, kk = i % BK;
            float v = 0.f;
            if (m0 + m < M && k0 + kk < K)
                v = A[(long)(m0 + m) * lda + (k0 + kk)];
            As[kk][m] = v;
        }
        // Load B tile (BK x BN)
#pragma unroll
        for (int it = 0; it < (BK * BN) / 256; it++) {
            int i = tid + it * 256;
            int kk = i / BN, n = i % BN;
            float v = 0.f;
            if (n0 + n < N && k0 + kk < K) {
                if (TRANS_B) v = B[(long)(n0 + n) * ldb + (k0 + kk)];
                else         v = B[(long)(k0 + kk) * ldb + (n0 + n)];
            }
            Bs[kk][n] = v;
        }
        __syncthreads();

#pragma unroll
        for (int kk = 0; kk < BK; kk++) {
            float a[8], b[8];
#pragma unroll
            for (int i = 0; i < 4; i++) {
                a[i]     = As[kk][ty * 4 + i];
                a[i + 4] = As[kk][64 + ty * 4 + i];
                b[i]     = Bs[kk][tx * 4 + i];
                b[i + 4] = Bs[kk][64 + tx * 4 + i];
            }
#pragma unroll
            for (int i = 0; i < 8; i++)
#pragma unroll
                for (int j = 0; j < 8; j++)
                    acc[i][j] += a[i] * b[j];
        }
        __syncthreads();
    }

#pragma unroll
    for (int i = 0; i < 8; i++) {
        int m = m0 + ((i < 4) ? (ty * 4 + i) : (64 + ty * 4 + (i - 4)));
        if (m >= M) continue;
#pragma unroll
        for (int j = 0; j < 8; j++) {
            int n = n0 + ((j < 4) ? (tx * 4 + j) : (64 + tx * 4 + (j - 4)));
            if (n >= N) continue;
            float v = alpha * acc[i][j];
            if (bias) v += bias[n];
            C[(long)m * ldc + n] = v;
        }
    }
}

// ---------------------------------------------------------------------------
// Adaptive avg pool of q (56x56 -> 12x12) per (b, channel)
// agent[b, p*12+q2, cc] = mean over q[b, y in bin(p), x in bin(q2), cc]
// ---------------------------------------------------------------------------
__global__ void pool_kernel(const float* __restrict__ QKV, float* __restrict__ AG)
{
    int idx = blockIdx.x * blockDim.x + threadIdx.x;
    const int total = B_ * AG_ * C_;
    if (idx >= total) return;
    int cc = idx & (C_ - 1);
    int a  = (idx >> 9) % AG_;
    int b  = idx / (AG_ * C_);
    int p  = a / PS_, q2 = a % PS_;
    int sy = (p * HH_) / PS_,  ey = ((p + 1) * HH_ + PS_ - 1) / PS_;
    int sx = (q2 * HH_) / PS_, ex = ((q2 + 1) * HH_ + PS_ - 1) / PS_;
    float s = 0.f;
    for (int y = sy; y < ey; y++)
        for (int x = sx; x < ex; x++)
            s += QKV[((long)(b * N_ + y * HH_ + x)) * (3 * C_) + cc];
    AG[idx] = s / (float)((ey - sy) * (ex - sx));
}

// ---------------------------------------------------------------------------
// Row softmax over length n (in place)
// ---------------------------------------------------------------------------
__global__ void softmax_rows(float* __restrict__ S, int n)
{
    long row = blockIdx.x;
    float* p = S + row * (long)n;
    __shared__ float red[256];
    int t = threadIdx.x;

    float m = -CUDART_INF_F;
    for (int i = t; i < n; i += 256) m = fmaxf(m, p[i]);
    red[t] = m; __syncthreads();
    for (int s = 128; s > 0; s >>= 1) {
        if (t < s) red[t] = fmaxf(red[t], red[t + s]);
        __syncthreads();
    }
    m = red[0]; __syncthreads();

    float sum = 0.f;
    for (int i = t; i < n; i += 256) {
        float e = __expf(p[i] - m);
        p[i] = e;
        sum += e;
    }
    red[t] = sum; __syncthreads();
    for (int s = 128; s > 0; s >>= 1) {
        if (t < s) red[t] += red[t + s];
        __syncthreads();
    }
    float inv = 1.f / red[0];
    for (int i = t; i < n; i += 256) p[i] *= inv;
}

// ---------------------------------------------------------------------------
// Fused stage 2: per (bh, query-tile of 32). softmax over 144 agents in-warp.
// out[b,l,h*64+dd] = sum_j softmax(scale * q.ah^T)[j] * agent_v[j,dd]
// ---------------------------------------------------------------------------
__global__ __launch_bounds__(256) void stage2_kernel(
    const float* __restrict__ QKV, const float* __restrict__ AG,
    const float* __restrict__ AV, float* __restrict__ ATTN)
{
    __shared__ float sA[AG_ * 65];   // pitch-65 (bank-conflict free on j-stride)
    int bh = blockIdx.y;
    int b = bh >> 3, h = bh & 7;
    int warp = threadIdx.x >> 5, lane = threadIdx.x & 31;

    // Phase A: sA <- ah (agent head slice)
    for (int i = threadIdx.x; i < AG_ * D_; i += 256) {
        int j = i >> 6, tt = i & 63;
        sA[j * 65 + tt] = AG[((long)(b * AG_) + j) * C_ + h * D_ + tt];
    }
    __syncthreads();

    float pq[4][5];
#pragma unroll
    for (int qi = 0; qi < 4; qi++) {
        int l = blockIdx.x * 32 + warp * 4 + qi;
        const float* qrow = QKV + ((long)(b * N_ + l)) * (3 * C_) + h * D_;
        float sc[5] = {0.f, 0.f, 0.f, 0.f, 0.f};
        for (int t = 0; t < D_; t++) {
            float qv = qrow[t];
#pragma unroll
            for (int s2 = 0; s2 < 5; s2++) {
                int j = lane + 32 * s2;
                if (j < AG_) sc[s2] += qv * sA[j * 65 + t];
            }
        }
        float mx = -CUDART_INF_F;
#pragma unroll
        for (int s2 = 0; s2 < 5; s2++) {
            int j = lane + 32 * s2;
            sc[s2] = (j < AG_) ? sc[s2] * SCALE_ : -CUDART_INF_F;
            mx = fmaxf(mx, sc[s2]);
        }
#pragma unroll
        for (int o = 16; o > 0; o >>= 1)
            mx = fmaxf(mx, __shfl_xor_sync(0xffffffffu, mx, o));
        float sum = 0.f;
#pragma unroll
        for (int s2 = 0; s2 < 5; s2++) {
            int j = lane + 32 * s2;
            float e = (j < AG_) ? __expf(sc[s2] - mx) : 0.f;
            sc[s2] = e;
            sum += e;
        }
#pragma unroll
        for (int o = 16; o > 0; o >>= 1)
            sum += __shfl_xor_sync(0xffffffffu, sum, o);
        float inv = 1.f / sum;
#pragma unroll
        for (int s2 = 0; s2 < 5; s2++) pq[qi][s2] = sc[s2] * inv;
    }
    __syncthreads();

    // Phase B: sA <- agent_v
    for (int i = threadIdx.x; i < AG_ * D_; i += 256) {
        int j = i >> 6, tt = i & 63;
        sA[j * 65 + tt] = AV[((long)bh * AG_ + j) * D_ + tt];
    }
    __syncthreads();

#pragma unroll
    for (int qi = 0; qi < 4; qi++) {
        float acc0 = 0.f, acc1 = 0.f;
#pragma unroll
        for (int s2 = 0; s2 < 5; s2++) {
            int jmax = (s2 < 4) ? 32 : (AG_ - 128);   // 16 for last group
            for (int jj = 0; jj < jmax; jj++) {
                float pv = __shfl_sync(0xffffffffu, pq[qi][s2], jj);
                int j = s2 * 32 + jj;
                acc0 += pv * sA[j * 65 + lane];
                acc1 += pv * sA[j * 65 + 32 + lane];
            }
        }
        int l = blockIdx.x * 32 + warp * 4 + qi;
        long base = ((long)(b * N_ + l)) * C_ + h * D_;
        ATTN[base + lane]      = acc0;
        ATTN[base + 32 + lane] = acc1;
    }
}

// ---------------------------------------------------------------------------
// Depthwise 3x3 conv on v image + bias, added into ATTN
// ---------------------------------------------------------------------------
__global__ void dwconv_kernel(const float* __restrict__ QKV,
                              const float* __restrict__ W,
                              const float* __restrict__ bias,
                              float* __restrict__ ATTN)
{
    long idx = (long)blockIdx.x * blockDim.x + threadIdx.x;
    const long total = (long)B_ * N_ * C_;
    if (idx >= total) return;
    int cc = (int)(idx & (C_ - 1));
    long sp = idx >> 9;
    int x = (int)(sp % HH_);
    long t2 = sp / HH_;
    int y = (int)(t2 % HH_);
    int b = (int)(t2 / HH_);

    float s = bias[cc];
#pragma unroll
    for (int dy = -1; dy <= 1; dy++) {
#pragma unroll
        for (int dx = -1; dx <= 1; dx++) {
            int yy = y + dy, xx = x + dx;
            if (yy >= 0 && yy < HH_ && xx >= 0 && xx < HH_) {
                s += QKV[((long)(b * N_ + yy * HH_ + xx)) * (3 * C_) + 2 * C_ + cc]
                     * W[cc * 9 + (dy + 1) * 3 + (dx + 1)];
            }
        }
    }
    ATTN[idx] += s;
}

// ---------------------------------------------------------------------------
extern "C" void kernel_launch(void* const* d_in, const int* in_sizes, int n_in,
                              void* d_out, int out_size)
{
    const float* x      = (const float*)d_in[0];
    const float* qkv_w  = (const float*)d_in[1];
    const float* proj_w = (const float*)d_in[2];
    const float* proj_b = (const float*)d_in[3];
    const float* dwc_w  = (const float*)d_in[4];
    const float* dwc_b  = (const float*)d_in[5];
    float* out = (float*)d_out;

    float *qkv, *ag, *s1, *av, *attn;
    cudaGetSymbolAddress((void**)&qkv,  g_qkv);
    cudaGetSymbolAddress((void**)&ag,   g_agent);
    cudaGetSymbolAddress((void**)&s1,   g_s1);
    cudaGetSymbolAddress((void**)&av,   g_av);
    cudaGetSymbolAddress((void**)&attn, g_attn);

    const int M = B_ * N_;            // 50176
    const int TC = 3 * C_;            // 1536

    // 1) QKV = x @ qkv_w^T   (M x 1536, K=512)
    {
        dim3 grid((TC + BN - 1) / BN, (M + BM - 1) / BM, 1);
        sgemm_kernel<true><<<grid, 256>>>(x, qkv_w, qkv,
            M, TC, C_, C_, C_, TC,
            0, 0, 0, 0, 0, 0, 1.0f, nullptr);
    }

    // 2) agent pooling from q
    {
        int total = B_ * AG_ * C_;
        pool_kernel<<<(total + 255) / 256, 256>>>(qkv, ag);
    }

    // 3a) S1 = scale * ah @ kh^T  batched over bh (M=144, N=3136, K=64)
    {
        dim3 grid((N_ + BN - 1) / BN, (AG_ + BM - 1) / BM, B_ * H_);
        sgemm_kernel<true><<<grid, 256>>>(ag, qkv + C_, s1,
            AG_, N_, D_, C_, TC, N_,
            (long)AG_ * C_, D_,                 // A: per-b, per-h
            (long)N_ * TC, D_,                  // B: per-b, per-h
            (long)H_ * AG_ * N_, (long)AG_ * N_, // C: per-b, per-h
            SCALE_, nullptr);
    }

    // 3b) softmax rows of S1 (128*144 rows of length 3136)
    softmax_rows<<<B_ * H_ * AG_, 256>>>(s1, N_);

    // 3c) agent_v = S1 @ vh  batched (M=144, N=64, K=3136)
    {
        dim3 grid(1, (AG_ + BM - 1) / BM, B_ * H_);
        sgemm_kernel<false><<<grid, 256>>>(s1, qkv + 2 * C_, av,
            AG_, D_, N_, N_, TC, D_,
            (long)H_ * AG_ * N_, (long)AG_ * N_,
            (long)N_ * TC, D_,
            (long)H_ * AG_ * D_, (long)AG_ * D_,
            1.0f, nullptr);
    }

    // 4) fused stage 2 -> ATTN (b, n, c)
    {
        dim3 grid(N_ / 32, B_ * H_, 1);
        stage2_kernel<<<grid, 256>>>(qkv, ag, av, attn);
    }

    // 5) depthwise conv residual add into ATTN
    {
        long total = (long)B_ * N_ * C_;
        dwconv_kernel<<<(unsigned)((total + 255) / 256), 256>>>(qkv, dwc_w, dwc_b, attn);
    }

    // 6) out = ATTN @ proj_w^T + proj_b
    {
        dim3 grid((C_ + BN - 1) / BN, (M + BM - 1) / BM, 1);
        sgemm_kernel<true><<<grid, 256>>>(attn, proj_w, out,
            M, C_, C_, C_, C_, C_,
            0, 0, 0, 0, 0, 0, 1.0f, proj_b);
    }
}

// round 8
// speedup vs baseline: 1.3692x; 1.3692x over previous
#include <cuda_runtime.h>
#include <cuda_bf16.h>
#include <math_constants.h>
#include <cstdint>

// Problem constants
#define B_   16
#define N_   3136
#define C_   512
#define H_   8
#define D_   64
#define HH_  56
#define AG_  144
#define PS_  12
#define SCALE_ 0.125f   // 64^-0.5

// Scratch (device globals; allocation-free rule)
__device__ float g_qkv[(size_t)B_ * N_ * 3 * C_];        // (b, n, 3c)
__device__ float g_agent[(size_t)B_ * AG_ * C_];          // (b, 144, c)
__device__ float g_s1[(size_t)B_ * H_ * AG_ * N_];        // (bh, 144, n)
__device__ float g_av[(size_t)B_ * H_ * AG_ * D_];        // (bh, 144, 64)
__device__ float g_attn[(size_t)B_ * N_ * C_];            // (b, n, c)

// ===========================================================================
// Warp-level mma.sync bf16 GEMM (works on base sm_103 PTX target).
// C[M,N] = alpha * A[M,K] @ op(B) (+ bias)
//   TRANS_B:  B stored row-major N x K  (computes A @ B^T)
//   !TRANS_B: B stored row-major K x N  (computes A @ B;   staged transposed)
// 3-pass bf16 split: hi*hi + hi*lo + lo*hi  (~1e-5 relative accuracy).
// Block tile 128x128, K-chunk 32, 8 warps (warp tile 64x32).
// Requirements: K % 32 == 0. M, N edge-guarded.
// ===========================================================================
__device__ __forceinline__ uint32_t smem_u32(const void* p) {
    uint32_t a;
    asm("{ .reg .u64 t; cvta.to.shared.u64 t, %1; cvt.u32.u64 %0, t; }"
        : "=r"(a) : "l"(p));
    return a;
}

#define STS128_(r0, r1, r2, r3, a) \
    asm volatile("st.shared.v4.b32 [%0], {%1, %2, %3, %4};" \
                 :: "r"(a), "r"(r0), "r"(r1), "r"(r2), "r"(r3) : "memory")

#define LDSM_X4(r0, r1, r2, r3, a) \
    asm volatile("ldmatrix.sync.aligned.m8n8.x4.shared.b16 {%0,%1,%2,%3}, [%4];" \
                 : "=r"(r0), "=r"(r1), "=r"(r2), "=r"(r3) : "r"(a))

#define MMA_BF16(c, a, b0, b1) \
    asm volatile("mma.sync.aligned.m16n8k16.row.col.f32.bf16.bf16.f32 " \
                 "{%0,%1,%2,%3}, {%4,%5,%6,%7}, {%8,%9}, {%0,%1,%2,%3};" \
                 : "+f"((c)[0]), "+f"((c)[1]), "+f"((c)[2]), "+f"((c)[3]) \
                 : "r"((a)[0]), "r"((a)[1]), "r"((a)[2]), "r"((a)[3]), \
                   "r"(b0), "r"(b1))

// smem region offsets (rows padded to 80 bytes: conflict-free ldmatrix)
#define SM_AHI 0
#define SM_ALO 10240
#define SM_BHI 20480
#define SM_BLO 30720
#define SM_TOT 40960

// convert 16 fp32 -> 8 packed bf16x2 hi + 8 lo, store 2x16B each
__device__ __forceinline__ void cvt_sts16(const float* f, uint32_t hiA, uint32_t loA)
{
    uint32_t hp[8], lp[8];
#pragma unroll
    for (int i = 0; i < 8; i++) {
        __nv_bfloat16 h0 = __float2bfloat16_rn(f[2 * i]);
        __nv_bfloat16 h1 = __float2bfloat16_rn(f[2 * i + 1]);
        float r0 = f[2 * i]     - __bfloat162float(h0);
        float r1 = f[2 * i + 1] - __bfloat162float(h1);
        __nv_bfloat16 l0 = __float2bfloat16_rn(r0);
        __nv_bfloat16 l1 = __float2bfloat16_rn(r1);
        hp[i] = (uint32_t)__bfloat16_as_ushort(h0) |
                ((uint32_t)__bfloat16_as_ushort(h1) << 16);
        lp[i] = (uint32_t)__bfloat16_as_ushort(l0) |
                ((uint32_t)__bfloat16_as_ushort(l1) << 16);
    }
    STS128_(hp[0], hp[1], hp[2], hp[3], hiA);
    STS128_(hp[4], hp[5], hp[6], hp[7], hiA + 16);
    STS128_(lp[0], lp[1], lp[2], lp[3], loA);
    STS128_(lp[4], lp[5], lp[6], lp[7], loA + 16);
}

template <bool TRANS_B>
__global__ __launch_bounds__(256, 2) void mma_gemm(
    const float* __restrict__ A, const float* __restrict__ B,
    float* __restrict__ C, const float* __restrict__ bias,
    int M, int N, int K, int lda, int ldb, int ldc,
    long sA_o, long sA_i, long sB_o, long sB_i, long sC_o, long sC_i,
    float alpha)
{
    __shared__ char sm[SM_TOT];
    uint32_t sb = smem_u32(sm);

    int batch = blockIdx.z;
    int bo = batch >> 3, bi = batch & 7;
    A += bo * sA_o + bi * sA_i;
    B += bo * sB_o + bi * sB_i;
    C += bo * sC_o + bi * sC_i;

    int m0 = blockIdx.y * 128;
    int n0 = blockIdx.x * 128;

    int tid = threadIdx.x, lane = tid & 31, wid = tid >> 5;
    int wm = (wid >> 2) * 64;     // warp row base within tile
    int wn = (wid & 3) * 32;      // warp col base within tile

    // ldmatrix per-lane row/column-half decode
    int s = lane >> 3;
    int arow = (s & 1) * 8 + (lane & 7);
    int akh  = (s >> 1) * 16;              // bytes
    int brow = (s >> 1) * 8 + (lane & 7);
    int bkh  = (s & 1) * 16;               // bytes

    float acc[4][4][4];
#pragma unroll
    for (int i = 0; i < 4; i++)
#pragma unroll
        for (int j = 0; j < 4; j++)
#pragma unroll
            for (int r = 0; r < 4; r++) acc[i][j][r] = 0.f;

    const int nch = K >> 5;
    for (int kc = 0; kc < nch; kc++) {
        __syncthreads();
        // ---- stage A tile (128 rows x 32 k) ----
        {
            int row = tid >> 1;
            int kb = (tid & 1) * 16;
            int mr = m0 + row; if (mr > M - 1) mr = M - 1;
            const float4* src = (const float4*)(A + (size_t)mr * lda + kc * 32 + kb);
            float f[16];
#pragma unroll
            for (int v = 0; v < 4; v++) {
                float4 t = src[v];
                f[v * 4 + 0] = t.x; f[v * 4 + 1] = t.y;
                f[v * 4 + 2] = t.z; f[v * 4 + 3] = t.w;
            }
            uint32_t off = (uint32_t)(row * 80 + kb * 2);
            cvt_sts16(f, sb + SM_AHI + off, sb + SM_ALO + off);
        }
        // ---- stage B tile into n-major [n][k] layout ----
        if (TRANS_B) {
            int row = tid >> 1;
            int kb = (tid & 1) * 16;
            int nr = n0 + row; if (nr > N - 1) nr = N - 1;
            const float4* src = (const float4*)(B + (size_t)nr * ldb + kc * 32 + kb);
            float f[16];
#pragma unroll
            for (int v = 0; v < 4; v++) {
                float4 t = src[v];
                f[v * 4 + 0] = t.x; f[v * 4 + 1] = t.y;
                f[v * 4 + 2] = t.z; f[v * 4 + 3] = t.w;
            }
            uint32_t off = (uint32_t)(row * 80 + kb * 2);
            cvt_sts16(f, sb + SM_BHI + off, sb + SM_BLO + off);
        } else {
            // B is K x N row-major; transpose while staging
            int kr = tid >> 3;              // 0..31 k row
            int nb = (tid & 7) * 16;        // n start
            const float* src = B + (size_t)(kc * 32 + kr) * ldb + n0 + nb;
            float f[16];
#pragma unroll
            for (int v = 0; v < 4; v++) {
                if (n0 + nb + v * 4 + 3 < N) {
                    float4 t = *(const float4*)(src + v * 4);
                    f[v * 4 + 0] = t.x; f[v * 4 + 1] = t.y;
                    f[v * 4 + 2] = t.z; f[v * 4 + 3] = t.w;
                } else {
#pragma unroll
                    for (int u = 0; u < 4; u++) {
                        int n = n0 + nb + v * 4 + u;
                        f[v * 4 + u] = (n < N) ? src[v * 4 + u] : 0.f;
                    }
                }
            }
            uint16_t* s16 = (uint16_t*)sm;
#pragma unroll
            for (int u = 0; u < 16; u++) {
                __nv_bfloat16 h = __float2bfloat16_rn(f[u]);
                float r = f[u] - __bfloat162float(h);
                __nv_bfloat16 l = __float2bfloat16_rn(r);
                int base = (nb + u) * 40 + kr;      // uint16 units (80B rows)
                s16[SM_BHI / 2 + base] = __bfloat16_as_ushort(h);
                s16[SM_BLO / 2 + base] = __bfloat16_as_ushort(l);
            }
        }
        __syncthreads();

        // ---- compute: 2 x k16 steps, 3 bf16 passes ----
#pragma unroll
        for (int k16 = 0; k16 < 2; k16++) {
            uint32_t koff = (uint32_t)(k16 * 32);
            uint32_t ah[4][4], bh[4][2], bl[4][2];
#pragma unroll
            for (int i = 0; i < 4; i++) {
                uint32_t a = sb + SM_AHI + (uint32_t)((wm + i * 16 + arow) * 80) + koff + akh;
                LDSM_X4(ah[i][0], ah[i][1], ah[i][2], ah[i][3], a);
            }
#pragma unroll
            for (int j2 = 0; j2 < 2; j2++) {
                uint32_t a = sb + SM_BHI + (uint32_t)((wn + j2 * 16 + brow) * 80) + koff + bkh;
                uint32_t r0, r1, r2, r3;
                LDSM_X4(r0, r1, r2, r3, a);
                bh[j2 * 2][0] = r0; bh[j2 * 2][1] = r1;
                bh[j2 * 2 + 1][0] = r2; bh[j2 * 2 + 1][1] = r3;
                a = sb + SM_BLO + (uint32_t)((wn + j2 * 16 + brow) * 80) + koff + bkh;
                LDSM_X4(r0, r1, r2, r3, a);
                bl[j2 * 2][0] = r0; bl[j2 * 2][1] = r1;
                bl[j2 * 2 + 1][0] = r2; bl[j2 * 2 + 1][1] = r3;
            }
            // pass 1: hi*hi   pass 2: hi*lo
#pragma unroll
            for (int i = 0; i < 4; i++)
#pragma unroll
                for (int j = 0; j < 4; j++) {
                    MMA_BF16(acc[i][j], ah[i], bh[j][0], bh[j][1]);
                    MMA_BF16(acc[i][j], ah[i], bl[j][0], bl[j][1]);
                }
            // pass 3: lo*hi
            uint32_t al[4][4];
#pragma unroll
            for (int i = 0; i < 4; i++) {
                uint32_t a = sb + SM_ALO + (uint32_t)((wm + i * 16 + arow) * 80) + koff + akh;
                LDSM_X4(al[i][0], al[i][1], al[i][2], al[i][3], a);
            }
#pragma unroll
            for (int i = 0; i < 4; i++)
#pragma unroll
                for (int j = 0; j < 4; j++)
                    MMA_BF16(acc[i][j], al[i], bh[j][0], bh[j][1]);
        }
    }

    // ---- epilogue: guarded fp32 stores ----
    int rq = lane >> 2, cq = (lane & 3) * 2;
#pragma unroll
    for (int i = 0; i < 4; i++) {
#pragma unroll
        for (int j = 0; j < 4; j++) {
            int r0 = m0 + wm + i * 16 + rq;
            int cc = n0 + wn + j * 8 + cq;
            if (cc >= N) continue;
            float bx = 0.f, by = 0.f;
            if (bias) { bx = bias[cc]; by = bias[cc + 1]; }
            if (r0 < M) {
                float2 v = make_float2(alpha * acc[i][j][0] + bx,
                                       alpha * acc[i][j][1] + by);
                *(float2*)(C + (size_t)r0 * ldc + cc) = v;
            }
            if (r0 + 8 < M) {
                float2 v = make_float2(alpha * acc[i][j][2] + bx,
                                       alpha * acc[i][j][3] + by);
                *(float2*)(C + (size_t)(r0 + 8) * ldc + cc) = v;
            }
        }
    }
}

// ---------------------------------------------------------------------------
// Adaptive avg pool of q (56x56 -> 12x12)
// ---------------------------------------------------------------------------
__global__ void pool_kernel(const float* __restrict__ QKV, float* __restrict__ AG)
{
    int idx = blockIdx.x * blockDim.x + threadIdx.x;
    const int total = B_ * AG_ * C_;
    if (idx >= total) return;
    int cc = idx & (C_ - 1);
    int a  = (idx >> 9) % AG_;
    int b  = idx / (AG_ * C_);
    int p  = a / PS_, q2 = a % PS_;
    int sy = (p * HH_) / PS_,  ey = ((p + 1) * HH_ + PS_ - 1) / PS_;
    int sx = (q2 * HH_) / PS_, ex = ((q2 + 1) * HH_ + PS_ - 1) / PS_;
    float s = 0.f;
    for (int y = sy; y < ey; y++)
        for (int x = sx; x < ex; x++)
            s += QKV[((long)(b * N_ + y * HH_ + x)) * (3 * C_) + cc];
    AG[idx] = s / (float)((ey - sy) * (ex - sx));
}

// ---------------------------------------------------------------------------
// Row softmax over length n (in place)
// ---------------------------------------------------------------------------
__global__ void softmax_rows(float* __restrict__ S, int n)
{
    long row = blockIdx.x;
    float* p = S + row * (long)n;
    __shared__ float red[256];
    int t = threadIdx.x;

    float m = -CUDART_INF_F;
    for (int i = t; i < n; i += 256) m = fmaxf(m, p[i]);
    red[t] = m; __syncthreads();
    for (int s = 128; s > 0; s >>= 1) {
        if (t < s) red[t] = fmaxf(red[t], red[t + s]);
        __syncthreads();
    }
    m = red[0]; __syncthreads();

    float sum = 0.f;
    for (int i = t; i < n; i += 256) {
        float e = __expf(p[i] - m);
        p[i] = e;
        sum += e;
    }
    red[t] = sum; __syncthreads();
    for (int s = 128; s > 0; s >>= 1) {
        if (t < s) red[t] += red[t + s];
        __syncthreads();
    }
    float inv = 1.f / red[0];
    for (int i = t; i < n; i += 256) p[i] *= inv;
}

// ---------------------------------------------------------------------------
// Fused stage 2: softmax over 144 agents in-warp + @agent_v
// ---------------------------------------------------------------------------
__global__ __launch_bounds__(256) void stage2_kernel(
    const float* __restrict__ QKV, const float* __restrict__ AG,
    const float* __restrict__ AV, float* __restrict__ ATTN)
{
    __shared__ float sA[AG_ * 65];
    int bh = blockIdx.y;
    int b = bh >> 3, h = bh & 7;
    int warp = threadIdx.x >> 5, lane = threadIdx.x & 31;

    for (int i = threadIdx.x; i < AG_ * D_; i += 256) {
        int j = i >> 6, tt = i & 63;
        sA[j * 65 + tt] = AG[((long)(b * AG_) + j) * C_ + h * D_ + tt];
    }
    __syncthreads();

    float pq[4][5];
#pragma unroll
    for (int qi = 0; qi < 4; qi++) {
        int l = blockIdx.x * 32 + warp * 4 + qi;
        const float* qrow = QKV + ((long)(b * N_ + l)) * (3 * C_) + h * D_;
        float sc[5] = {0.f, 0.f, 0.f, 0.f, 0.f};
        for (int t = 0; t < D_; t++) {
            float qv = qrow[t];
#pragma unroll
            for (int s2 = 0; s2 < 5; s2++) {
                int j = lane + 32 * s2;
                if (j < AG_) sc[s2] += qv * sA[j * 65 + t];
            }
        }
        float mx = -CUDART_INF_F;
#pragma unroll
        for (int s2 = 0; s2 < 5; s2++) {
            int j = lane + 32 * s2;
            sc[s2] = (j < AG_) ? sc[s2] * SCALE_ : -CUDART_INF_F;
            mx = fmaxf(mx, sc[s2]);
        }
#pragma unroll
        for (int o = 16; o > 0; o >>= 1)
            mx = fmaxf(mx, __shfl_xor_sync(0xffffffffu, mx, o));
        float sum = 0.f;
#pragma unroll
        for (int s2 = 0; s2 < 5; s2++) {
            int j = lane + 32 * s2;
            float e = (j < AG_) ? __expf(sc[s2] - mx) : 0.f;
            sc[s2] = e;
            sum += e;
        }
#pragma unroll
        for (int o = 16; o > 0; o >>= 1)
            sum += __shfl_xor_sync(0xffffffffu, sum, o);
        float inv = 1.f / sum;
#pragma unroll
        for (int s2 = 0; s2 < 5; s2++) pq[qi][s2] = sc[s2] * inv;
    }
    __syncthreads();

    for (int i = threadIdx.x; i < AG_ * D_; i += 256) {
        int j = i >> 6, tt = i & 63;
        sA[j * 65 + tt] = AV[((long)bh * AG_ + j) * D_ + tt];
    }
    __syncthreads();

#pragma unroll
    for (int qi = 0; qi < 4; qi++) {
        float acc0 = 0.f, acc1 = 0.f;
#pragma unroll
        for (int s2 = 0; s2 < 5; s2++) {
            int jmax = (s2 < 4) ? 32 : (AG_ - 128);
            for (int jj = 0; jj < jmax; jj++) {
                float pv = __shfl_sync(0xffffffffu, pq[qi][s2], jj);
                int j = s2 * 32 + jj;
                acc0 += pv * sA[j * 65 + lane];
                acc1 += pv * sA[j * 65 + 32 + lane];
            }
        }
        int l = blockIdx.x * 32 + warp * 4 + qi;
        long base = ((long)(b * N_ + l)) * C_ + h * D_;
        ATTN[base + lane]      = acc0;
        ATTN[base + 32 + lane] = acc1;
    }
}

// ---------------------------------------------------------------------------
// Depthwise 3x3 conv on v image + bias, added into ATTN
// ---------------------------------------------------------------------------
__global__ void dwconv_kernel(const float* __restrict__ QKV,
                              const float* __restrict__ W,
                              const float* __restrict__ bias,
                              float* __restrict__ ATTN)
{
    long idx = (long)blockIdx.x * blockDim.x + threadIdx.x;
    const long total = (long)B_ * N_ * C_;
    if (idx >= total) return;
    int cc = (int)(idx & (C_ - 1));
    long sp = idx >> 9;
    int x = (int)(sp % HH_);
    long t2 = sp / HH_;
    int y = (int)(t2 % HH_);
    int b = (int)(t2 / HH_);

    float s = bias[cc];
#pragma unroll
    for (int dy = -1; dy <= 1; dy++) {
#pragma unroll
        for (int dx = -1; dx <= 1; dx++) {
            int yy = y + dy, xx = x + dx;
            if (yy >= 0 && yy < HH_ && xx >= 0 && xx < HH_) {
                s += QKV[((long)(b * N_ + yy * HH_ + xx)) * (3 * C_) + 2 * C_ + cc]
                     * W[cc * 9 + (dy + 1) * 3 + (dx + 1)];
            }
        }
    }
    ATTN[idx] += s;
}

// ---------------------------------------------------------------------------
extern "C" void kernel_launch(void* const* d_in, const int* in_sizes, int n_in,
                              void* d_out, int out_size)
{
    const float* x      = (const float*)d_in[0];
    const float* qkv_w  = (const float*)d_in[1];
    const float* proj_w = (const float*)d_in[2];
    const float* proj_b = (const float*)d_in[3];
    const float* dwc_w  = (const float*)d_in[4];
    const float* dwc_b  = (const float*)d_in[5];
    float* out = (float*)d_out;

    float *qkv, *ag, *s1, *av, *attn;
    cudaGetSymbolAddress((void**)&qkv,  g_qkv);
    cudaGetSymbolAddress((void**)&ag,   g_agent);
    cudaGetSymbolAddress((void**)&s1,   g_s1);
    cudaGetSymbolAddress((void**)&av,   g_av);
    cudaGetSymbolAddress((void**)&attn, g_attn);

    const int M = B_ * N_;            // 50176
    const int TC = 3 * C_;            // 1536

    // 1) QKV = x @ qkv_w^T  (mma bf16 3-pass)
    {
        dim3 grid(TC / 128, M / 128, 1);
        mma_gemm<true><<<grid, 256>>>(x, qkv_w, qkv, nullptr,
            M, TC, C_, C_, C_, TC,
            0, 0, 0, 0, 0, 0, 1.0f);
    }

    // 2) agent pooling from q
    {
        int total = B_ * AG_ * C_;
        pool_kernel<<<(total + 255) / 256, 256>>>(qkv, ag);
    }

    // 3a) S1 = scale * ah @ kh^T  batched over bh (M=144, N=3136, K=64)
    {
        dim3 grid((N_ + 127) / 128, (AG_ + 127) / 128, B_ * H_);
        mma_gemm<true><<<grid, 256>>>(ag, qkv + C_, s1, nullptr,
            AG_, N_, D_, C_, TC, N_,
            (long)AG_ * C_, D_,
            (long)N_ * TC, D_,
            (long)H_ * AG_ * N_, (long)AG_ * N_,
            SCALE_);
    }

    // 3b) softmax rows of S1
    softmax_rows<<<B_ * H_ * AG_, 256>>>(s1, N_);

    // 3c) agent_v = S1 @ vh  batched (M=144, N=64, K=3136)
    {
        dim3 grid(1, (AG_ + 127) / 128, B_ * H_);
        mma_gemm<false><<<grid, 256>>>(s1, qkv + 2 * C_, av, nullptr,
            AG_, D_, N_, N_, TC, D_,
            (long)H_ * AG_ * N_, (long)AG_ * N_,
            (long)N_ * TC, D_,
            (long)H_ * AG_ * D_, (long)AG_ * D_,
            1.0f);
    }

    // 4) fused stage 2 -> ATTN (b, n, c)
    {
        dim3 grid(N_ / 32, B_ * H_, 1);
        stage2_kernel<<<grid, 256>>>(qkv, ag, av, attn);
    }

    // 5) depthwise conv residual add into ATTN
    {
        long total = (long)B_ * N_ * C_;
        dwconv_kernel<<<(unsigned)((total + 255) / 256), 256>>>(qkv, dwc_w, dwc_b, attn);
    }

    // 6) out = ATTN @ proj_w^T + proj_b  (mma bf16 3-pass)
    {
        dim3 grid(C_ / 128, M / 128, 1);
        mma_gemm<true><<<grid, 256>>>(attn, proj_w, out, proj_b,
            M, C_, C_, C_, C_, C_,
            0, 0, 0, 0, 0, 0, 1.0f);
    }
}

// round 9
// speedup vs baseline: 1.8417x; 1.3451x over previous
#include <cuda_runtime.h>
#include <cuda_bf16.h>
#include <math_constants.h>
#include <cstdint>

// Problem constants
#define B_   16
#define N_   3136
#define C_   512
#define H_   8
#define D_   64
#define HH_  56
#define AG_  144
#define PS_  12
#define SCALE_ 0.125f   // 64^-0.5

// Scratch (device globals; allocation-free rule)
__device__ float g_qkv[(size_t)B_ * N_ * 3 * C_];        // (b, n, 3c)
__device__ float g_agent[(size_t)B_ * AG_ * C_];          // (b, 144, c)
__device__ float g_s1[(size_t)B_ * H_ * AG_ * N_];        // (bh, 144, n)
__device__ float g_av[(size_t)B_ * H_ * AG_ * D_];        // (bh, 144, 64)
__device__ float g_attn[(size_t)B_ * N_ * C_];            // (b, n, c)

// ===========================================================================
// Warp-level mma.sync bf16 GEMM (base sm_103 PTX target), double-buffered.
// C[M,N] = alpha * A[M,K] @ op(B) (+ bias)
//   TRANS_B:  B stored row-major N x K  (A @ B^T)
//   !TRANS_B: B stored row-major K x N  (A @ B; staged transposed)
// 3-pass bf16 split (hi*hi + hi*lo + lo*hi), ~1e-5 accuracy.
// Block tile 128x128, K-chunk 32, 8 warps (warp tile 64x32), 2 smem stages.
// ===========================================================================
__device__ __forceinline__ uint32_t smem_u32(const void* p) {
    uint32_t a;
    asm("{ .reg .u64 t; cvta.to.shared.u64 t, %1; cvt.u32.u64 %0, t; }"
        : "=r"(a) : "l"(p));
    return a;
}

#define STS128_(r0, r1, r2, r3, a) \
    asm volatile("st.shared.v4.b32 [%0], {%1, %2, %3, %4};" \
                 :: "r"(a), "r"(r0), "r"(r1), "r"(r2), "r"(r3) : "memory")

#define LDSM_X4(r0, r1, r2, r3, a) \
    asm volatile("ldmatrix.sync.aligned.m8n8.x4.shared.b16 {%0,%1,%2,%3}, [%4];" \
                 : "=r"(r0), "=r"(r1), "=r"(r2), "=r"(r3) : "r"(a))

#define MMA_BF16(c, a, b0, b1) \
    asm volatile("mma.sync.aligned.m16n8k16.row.col.f32.bf16.bf16.f32 " \
                 "{%0,%1,%2,%3}, {%4,%5,%6,%7}, {%8,%9}, {%0,%1,%2,%3};" \
                 : "+f"((c)[0]), "+f"((c)[1]), "+f"((c)[2]), "+f"((c)[3]) \
                 : "r"((a)[0]), "r"((a)[1]), "r"((a)[2]), "r"((a)[3]), \
                   "r"(b0), "r"(b1))

// per-stage smem layout (rows padded to 80B: conflict-free ldmatrix)
#define SM_AHI 0
#define SM_ALO 10240
#define SM_BHI 20480
#define SM_BLO 30720
#define STAGE_SZ 40960
#define SM_TOT (2 * STAGE_SZ)

// convert 16 fp32 -> 8 packed bf16x2 hi + 8 lo, store 2x16B each
__device__ __forceinline__ void cvt_sts16(const float* f, uint32_t hiA, uint32_t loA)
{
    uint32_t hp[8], lp[8];
#pragma unroll
    for (int i = 0; i < 8; i++) {
        __nv_bfloat16 h0 = __float2bfloat16_rn(f[2 * i]);
        __nv_bfloat16 h1 = __float2bfloat16_rn(f[2 * i + 1]);
        float r0 = f[2 * i]     - __bfloat162float(h0);
        float r1 = f[2 * i + 1] - __bfloat162float(h1);
        __nv_bfloat16 l0 = __float2bfloat16_rn(r0);
        __nv_bfloat16 l1 = __float2bfloat16_rn(r1);
        hp[i] = (uint32_t)__bfloat16_as_ushort(h0) |
                ((uint32_t)__bfloat16_as_ushort(h1) << 16);
        lp[i] = (uint32_t)__bfloat16_as_ushort(l0) |
                ((uint32_t)__bfloat16_as_ushort(l1) << 16);
    }
    STS128_(hp[0], hp[1], hp[2], hp[3], hiA);
    STS128_(hp[4], hp[5], hp[6], hp[7], hiA + 16);
    STS128_(lp[0], lp[1], lp[2], lp[3], loA);
    STS128_(lp[4], lp[5], lp[6], lp[7], loA + 16);
}

template <bool TRANS_B>
__global__ __launch_bounds__(256) void mma_gemm(
    const float* __restrict__ A, const float* __restrict__ B,
    float* __restrict__ C, const float* __restrict__ bias,
    int M, int N, int K, int lda, int ldb, int ldc,
    long sA_o, long sA_i, long sB_o, long sB_i, long sC_o, long sC_i,
    float alpha)
{
    extern __shared__ char sm[];
    uint32_t sb = smem_u32(sm);

    int batch = blockIdx.z;
    int bo = batch >> 3, bi = batch & 7;
    A += bo * sA_o + bi * sA_i;
    B += bo * sB_o + bi * sB_i;
    C += bo * sC_o + bi * sC_i;

    int m0 = blockIdx.y * 128;
    int n0 = blockIdx.x * 128;

    int tid = threadIdx.x, lane = tid & 31, wid = tid >> 5;
    int wm = (wid >> 2) * 64;     // warp row base
    int wn = (wid & 3) * 32;      // warp col base

    int s = lane >> 3;
    int arow = (s & 1) * 8 + (lane & 7);
    int akh  = (s >> 1) * 16;              // bytes
    int brow = (s >> 1) * 8 + (lane & 7);
    int bkh  = (s & 1) * 16;               // bytes

    // staging indices
    int srow = tid >> 1;
    int skb  = (tid & 1) * 16;
    int mr = m0 + srow; if (mr > M - 1) mr = M - 1;
    const float* Ab = A + (size_t)mr * lda + skb;
    uint32_t aoff = (uint32_t)(srow * 80 + skb * 2);

    const float* Bb = nullptr;
    int kr = 0, nb = 0;
    if (TRANS_B) {
        int nr = n0 + srow; if (nr > N - 1) nr = N - 1;
        Bb = B + (size_t)nr * ldb + skb;
    } else {
        kr = tid >> 3;                // 0..31
        nb = (tid & 7) * 16;          // n start
        Bb = B + (size_t)kr * ldb + n0 + nb;
    }

    float acc[4][4][4];
#pragma unroll
    for (int i = 0; i < 4; i++)
#pragma unroll
        for (int j = 0; j < 4; j++)
#pragma unroll
            for (int r = 0; r < 4; r++) acc[i][j][r] = 0.f;

    float fA[16], fB[16];
    const int nch = K >> 5;

    // ---- prefetch + stage chunk 0 ----
    {
        const float4* s4 = (const float4*)(Ab);
#pragma unroll
        for (int v = 0; v < 4; v++) {
            float4 t = s4[v];
            fA[v * 4 + 0] = t.x; fA[v * 4 + 1] = t.y;
            fA[v * 4 + 2] = t.z; fA[v * 4 + 3] = t.w;
        }
        if (TRANS_B) {
            const float4* b4 = (const float4*)(Bb);
#pragma unroll
            for (int v = 0; v < 4; v++) {
                float4 t = b4[v];
                fB[v * 4 + 0] = t.x; fB[v * 4 + 1] = t.y;
                fB[v * 4 + 2] = t.z; fB[v * 4 + 3] = t.w;
            }
        } else {
#pragma unroll
            for (int v = 0; v < 4; v++) {
                if (n0 + nb + v * 4 + 3 < N) {
                    float4 t = *(const float4*)(Bb + v * 4);
                    fB[v * 4 + 0] = t.x; fB[v * 4 + 1] = t.y;
                    fB[v * 4 + 2] = t.z; fB[v * 4 + 3] = t.w;
                } else {
#pragma unroll
                    for (int u = 0; u < 4; u++) {
                        int n = n0 + nb + v * 4 + u;
                        fB[v * 4 + u] = (n < N) ? Bb[v * 4 + u] : 0.f;
                    }
                }
            }
        }
        cvt_sts16(fA, sb + SM_AHI + aoff, sb + SM_ALO + aoff);
        if (TRANS_B) {
            cvt_sts16(fB, sb + SM_BHI + aoff, sb + SM_BLO + aoff);
        } else {
            uint16_t* s16 = (uint16_t*)sm;
#pragma unroll
            for (int u = 0; u < 16; u++) {
                __nv_bfloat16 h = __float2bfloat16_rn(fB[u]);
                float r = fB[u] - __bfloat162float(h);
                __nv_bfloat16 l = __float2bfloat16_rn(r);
                int base = (nb + u) * 40 + kr;
                s16[SM_BHI / 2 + base] = __bfloat16_as_ushort(h);
                s16[SM_BLO / 2 + base] = __bfloat16_as_ushort(l);
            }
        }
    }

    for (int kc = 0; kc < nch; kc++) {
        __syncthreads();
        uint32_t st = sb + (uint32_t)((kc & 1) * STAGE_SZ);
        bool more = (kc + 1 < nch);

        // ---- prefetch chunk kc+1 into regs (latency hidden by MMAs) ----
        if (more) {
            const float4* s4 = (const float4*)(Ab + (size_t)(kc + 1) * 32);
#pragma unroll
            for (int v = 0; v < 4; v++) {
                float4 t = s4[v];
                fA[v * 4 + 0] = t.x; fA[v * 4 + 1] = t.y;
                fA[v * 4 + 2] = t.z; fA[v * 4 + 3] = t.w;
            }
            if (TRANS_B) {
                const float4* b4 = (const float4*)(Bb + (size_t)(kc + 1) * 32);
#pragma unroll
                for (int v = 0; v < 4; v++) {
                    float4 t = b4[v];
                    fB[v * 4 + 0] = t.x; fB[v * 4 + 1] = t.y;
                    fB[v * 4 + 2] = t.z; fB[v * 4 + 3] = t.w;
                }
            } else {
                const float* bp = Bb + (size_t)(kc + 1) * 32 * ldb;
#pragma unroll
                for (int v = 0; v < 4; v++) {
                    if (n0 + nb + v * 4 + 3 < N) {
                        float4 t = *(const float4*)(bp + v * 4);
                        fB[v * 4 + 0] = t.x; fB[v * 4 + 1] = t.y;
                        fB[v * 4 + 2] = t.z; fB[v * 4 + 3] = t.w;
                    } else {
#pragma unroll
                        for (int u = 0; u < 4; u++) {
                            int n = n0 + nb + v * 4 + u;
                            fB[v * 4 + u] = (n < N) ? bp[v * 4 + u] : 0.f;
                        }
                    }
                }
            }
        }

        // ---- MMAs on stage kc&1 ----
#pragma unroll
        for (int k16 = 0; k16 < 2; k16++) {
            uint32_t koff = (uint32_t)(k16 * 32);
            uint32_t ah[4][4], bh[4][2], bl[4][2];
#pragma unroll
            for (int i = 0; i < 4; i++) {
                uint32_t a = st + SM_AHI + (uint32_t)((wm + i * 16 + arow) * 80) + koff + akh;
                LDSM_X4(ah[i][0], ah[i][1], ah[i][2], ah[i][3], a);
            }
#pragma unroll
            for (int j2 = 0; j2 < 2; j2++) {
                uint32_t a = st + SM_BHI + (uint32_t)((wn + j2 * 16 + brow) * 80) + koff + bkh;
                uint32_t r0, r1, r2, r3;
                LDSM_X4(r0, r1, r2, r3, a);
                bh[j2 * 2][0] = r0; bh[j2 * 2][1] = r1;
                bh[j2 * 2 + 1][0] = r2; bh[j2 * 2 + 1][1] = r3;
                a = st + SM_BLO + (uint32_t)((wn + j2 * 16 + brow) * 80) + koff + bkh;
                LDSM_X4(r0, r1, r2, r3, a);
                bl[j2 * 2][0] = r0; bl[j2 * 2][1] = r1;
                bl[j2 * 2 + 1][0] = r2; bl[j2 * 2 + 1][1] = r3;
            }
#pragma unroll
            for (int i = 0; i < 4; i++)
#pragma unroll
                for (int j = 0; j < 4; j++) {
                    MMA_BF16(acc[i][j], ah[i], bh[j][0], bh[j][1]);
                    MMA_BF16(acc[i][j], ah[i], bl[j][0], bl[j][1]);
                }
            uint32_t al[4][4];
#pragma unroll
            for (int i = 0; i < 4; i++) {
                uint32_t a = st + SM_ALO + (uint32_t)((wm + i * 16 + arow) * 80) + koff + akh;
                LDSM_X4(al[i][0], al[i][1], al[i][2], al[i][3], a);
            }
#pragma unroll
            for (int i = 0; i < 4; i++)
#pragma unroll
                for (int j = 0; j < 4; j++)
                    MMA_BF16(acc[i][j], al[i], bh[j][0], bh[j][1]);
        }

        // ---- convert + store chunk kc+1 into other stage ----
        if (more) {
            uint32_t st2 = sb + (uint32_t)(((kc + 1) & 1) * STAGE_SZ);
            int so2 = ((kc + 1) & 1) * STAGE_SZ;
            cvt_sts16(fA, st2 + SM_AHI + aoff, st2 + SM_ALO + aoff);
            if (TRANS_B) {
                cvt_sts16(fB, st2 + SM_BHI + aoff, st2 + SM_BLO + aoff);
            } else {
                uint16_t* s16 = (uint16_t*)(sm + so2);
#pragma unroll
                for (int u = 0; u < 16; u++) {
                    __nv_bfloat16 h = __float2bfloat16_rn(fB[u]);
                    float r = fB[u] - __bfloat162float(h);
                    __nv_bfloat16 l = __float2bfloat16_rn(r);
                    int base = (nb + u) * 40 + kr;
                    s16[SM_BHI / 2 + base] = __bfloat16_as_ushort(h);
                    s16[SM_BLO / 2 + base] = __bfloat16_as_ushort(l);
                }
            }
        }
    }

    // ---- epilogue: guarded fp32 stores ----
    int rq = lane >> 2, cq = (lane & 3) * 2;
#pragma unroll
    for (int i = 0; i < 4; i++) {
#pragma unroll
        for (int j = 0; j < 4; j++) {
            int r0 = m0 + wm + i * 16 + rq;
            int cc = n0 + wn + j * 8 + cq;
            if (cc >= N) continue;
            float bx = 0.f, by = 0.f;
            if (bias) { bx = bias[cc]; by = bias[cc + 1]; }
            if (r0 < M) {
                float2 v = make_float2(alpha * acc[i][j][0] + bx,
                                       alpha * acc[i][j][1] + by);
                *(float2*)(C + (size_t)r0 * ldc + cc) = v;
            }
            if (r0 + 8 < M) {
                float2 v = make_float2(alpha * acc[i][j][2] + bx,
                                       alpha * acc[i][j][3] + by);
                *(float2*)(C + (size_t)(r0 + 8) * ldc + cc) = v;
            }
        }
    }
}

// ---------------------------------------------------------------------------
// Adaptive avg pool of q (56x56 -> 12x12)
// ---------------------------------------------------------------------------
__global__ void pool_kernel(const float* __restrict__ QKV, float* __restrict__ AG)
{
    int idx = blockIdx.x * blockDim.x + threadIdx.x;
    const int total = B_ * AG_ * C_;
    if (idx >= total) return;
    int cc = idx & (C_ - 1);
    int a  = (idx >> 9) % AG_;
    int b  = idx / (AG_ * C_);
    int p  = a / PS_, q2 = a % PS_;
    int sy = (p * HH_) / PS_,  ey = ((p + 1) * HH_ + PS_ - 1) / PS_;
    int sx = (q2 * HH_) / PS_, ex = ((q2 + 1) * HH_ + PS_ - 1) / PS_;
    float s = 0.f;
    for (int y = sy; y < ey; y++)
        for (int x = sx; x < ex; x++)
            s += QKV[((long)(b * N_ + y * HH_ + x)) * (3 * C_) + cc];
    AG[idx] = s / (float)((ey - sy) * (ex - sx));
}

// ---------------------------------------------------------------------------
// Row softmax over length n (in place)
// ---------------------------------------------------------------------------
__global__ void softmax_rows(float* __restrict__ S, int n)
{
    long row = blockIdx.x;
    float* p = S + row * (long)n;
    __shared__ float red[256];
    int t = threadIdx.x;

    float m = -CUDART_INF_F;
    for (int i = t; i < n; i += 256) m = fmaxf(m, p[i]);
    red[t] = m; __syncthreads();
    for (int s = 128; s > 0; s >>= 1) {
        if (t < s) red[t] = fmaxf(red[t], red[t + s]);
        __syncthreads();
    }
    m = red[0]; __syncthreads();

    float sum = 0.f;
    for (int i = t; i < n; i += 256) {
        float e = __expf(p[i] - m);
        p[i] = e;
        sum += e;
    }
    red[t] = sum; __syncthreads();
    for (int s = 128; s > 0; s >>= 1) {
        if (t < s) red[t] += red[t + s];
        __syncthreads();
    }
    float inv = 1.f / red[0];
    for (int i = t; i < n; i += 256) p[i] *= inv;
}

// ---------------------------------------------------------------------------
// Fused stage 2: softmax over 144 agents in-warp + @agent_v
// ---------------------------------------------------------------------------
__global__ __launch_bounds__(256) void stage2_kernel(
    const float* __restrict__ QKV, const float* __restrict__ AG,
    const float* __restrict__ AV, float* __restrict__ ATTN)
{
    __shared__ float sA[AG_ * 65];
    int bh = blockIdx.y;
    int b = bh >> 3, h = bh & 7;
    int warp = threadIdx.x >> 5, lane = threadIdx.x & 31;

    for (int i = threadIdx.x; i < AG_ * D_; i += 256) {
        int j = i >> 6, tt = i & 63;
        sA[j * 65 + tt] = AG[((long)(b * AG_) + j) * C_ + h * D_ + tt];
    }
    __syncthreads();

    float pq[4][5];
#pragma unroll
    for (int qi = 0; qi < 4; qi++) {
        int l = blockIdx.x * 32 + warp * 4 + qi;
        const float* qrow = QKV + ((long)(b * N_ + l)) * (3 * C_) + h * D_;
        float sc[5] = {0.f, 0.f, 0.f, 0.f, 0.f};
        for (int t = 0; t < D_; t++) {
            float qv = qrow[t];
#pragma unroll
            for (int s2 = 0; s2 < 5; s2++) {
                int j = lane + 32 * s2;
                if (j < AG_) sc[s2] += qv * sA[j * 65 + t];
            }
        }
        float mx = -CUDART_INF_F;
#pragma unroll
        for (int s2 = 0; s2 < 5; s2++) {
            int j = lane + 32 * s2;
            sc[s2] = (j < AG_) ? sc[s2] * SCALE_ : -CUDART_INF_F;
            mx = fmaxf(mx, sc[s2]);
        }
#pragma unroll
        for (int o = 16; o > 0; o >>= 1)
            mx = fmaxf(mx, __shfl_xor_sync(0xffffffffu, mx, o));
        float sum = 0.f;
#pragma unroll
        for (int s2 = 0; s2 < 5; s2++) {
            int j = lane + 32 * s2;
            float e = (j < AG_) ? __expf(sc[s2] - mx) : 0.f;
            sc[s2] = e;
            sum += e;
        }
#pragma unroll
        for (int o = 16; o > 0; o >>= 1)
            sum += __shfl_xor_sync(0xffffffffu, sum, o);
        float inv = 1.f / sum;
#pragma unroll
        for (int s2 = 0; s2 < 5; s2++) pq[qi][s2] = sc[s2] * inv;
    }
    __syncthreads();

    for (int i = threadIdx.x; i < AG_ * D_; i += 256) {
        int j = i >> 6, tt = i & 63;
        sA[j * 65 + tt] = AV[((long)bh * AG_ + j) * D_ + tt];
    }
    __syncthreads();

#pragma unroll
    for (int qi = 0; qi < 4; qi++) {
        float acc0 = 0.f, acc1 = 0.f;
#pragma unroll
        for (int s2 = 0; s2 < 5; s2++) {
            int jmax = (s2 < 4) ? 32 : (AG_ - 128);
            for (int jj = 0; jj < jmax; jj++) {
                float pv = __shfl_sync(0xffffffffu, pq[qi][s2], jj);
                int j = s2 * 32 + jj;
                acc0 += pv * sA[j * 65 + lane];
                acc1 += pv * sA[j * 65 + 32 + lane];
            }
        }
        int l = blockIdx.x * 32 + warp * 4 + qi;
        long base = ((long)(b * N_ + l)) * C_ + h * D_;
        ATTN[base + lane]      = acc0;
        ATTN[base + 32 + lane] = acc1;
    }
}

// ---------------------------------------------------------------------------
// Depthwise 3x3 conv on v image + bias, added into ATTN
// ---------------------------------------------------------------------------
__global__ void dwconv_kernel(const float* __restrict__ QKV,
                              const float* __restrict__ W,
                              const float* __restrict__ bias,
                              float* __restrict__ ATTN)
{
    long idx = (long)blockIdx.x * blockDim.x + threadIdx.x;
    const long total = (long)B_ * N_ * C_;
    if (idx >= total) return;
    int cc = (int)(idx & (C_ - 1));
    long sp = idx >> 9;
    int x = (int)(sp % HH_);
    long t2 = sp / HH_;
    int y = (int)(t2 % HH_);
    int b = (int)(t2 / HH_);

    float s = bias[cc];
#pragma unroll
    for (int dy = -1; dy <= 1; dy++) {
#pragma unroll
        for (int dx = -1; dx <= 1; dx++) {
            int yy = y + dy, xx = x + dx;
            if (yy >= 0 && yy < HH_ && xx >= 0 && xx < HH_) {
                s += QKV[((long)(b * N_ + yy * HH_ + xx)) * (3 * C_) + 2 * C_ + cc]
                     * W[cc * 9 + (dy + 1) * 3 + (dx + 1)];
            }
        }
    }
    ATTN[idx] += s;
}

// ---------------------------------------------------------------------------
extern "C" void kernel_launch(void* const* d_in, const int* in_sizes, int n_in,
                              void* d_out, int out_size)
{
    const float* x      = (const float*)d_in[0];
    const float* qkv_w  = (const float*)d_in[1];
    const float* proj_w = (const float*)d_in[2];
    const float* proj_b = (const float*)d_in[3];
    const float* dwc_w  = (const float*)d_in[4];
    const float* dwc_b  = (const float*)d_in[5];
    float* out = (float*)d_out;

    float *qkv, *ag, *s1, *av, *attn;
    cudaGetSymbolAddress((void**)&qkv,  g_qkv);
    cudaGetSymbolAddress((void**)&ag,   g_agent);
    cudaGetSymbolAddress((void**)&s1,   g_s1);
    cudaGetSymbolAddress((void**)&av,   g_av);
    cudaGetSymbolAddress((void**)&attn, g_attn);

    cudaFuncSetAttribute(mma_gemm<true>,  cudaFuncAttributeMaxDynamicSharedMemorySize, SM_TOT);
    cudaFuncSetAttribute(mma_gemm<false>, cudaFuncAttributeMaxDynamicSharedMemorySize, SM_TOT);

    const int M = B_ * N_;            // 50176
    const int TC = 3 * C_;            // 1536

    // 1) QKV = x @ qkv_w^T  (mma bf16 3-pass, pipelined)
    {
        dim3 grid(TC / 128, M / 128, 1);
        mma_gemm<true><<<grid, 256, SM_TOT>>>(x, qkv_w, qkv, nullptr,
            M, TC, C_, C_, C_, TC,
            0, 0, 0, 0, 0, 0, 1.0f);
    }

    // 2) agent pooling from q
    {
        int total = B_ * AG_ * C_;
        pool_kernel<<<(total + 255) / 256, 256>>>(qkv, ag);
    }

    // 3a) S1 = scale * ah @ kh^T  batched over bh (M=144, N=3136, K=64)
    {
        dim3 grid((N_ + 127) / 128, (AG_ + 127) / 128, B_ * H_);
        mma_gemm<true><<<grid, 256, SM_TOT>>>(ag, qkv + C_, s1, nullptr,
            AG_, N_, D_, C_, TC, N_,
            (long)AG_ * C_, D_,
            (long)N_ * TC, D_,
            (long)H_ * AG_ * N_, (long)AG_ * N_,
            SCALE_);
    }

    // 3b) softmax rows of S1
    softmax_rows<<<B_ * H_ * AG_, 256>>>(s1, N_);

    // 3c) agent_v = S1 @ vh  batched (M=144, N=64, K=3136)
    {
        dim3 grid(1, (AG_ + 127) / 128, B_ * H_);
        mma_gemm<false><<<grid, 256, SM_TOT>>>(s1, qkv + 2 * C_, av, nullptr,
            AG_, D_, N_, N_, TC, D_,
            (long)H_ * AG_ * N_, (long)AG_ * N_,
            (long)N_ * TC, D_,
            (long)H_ * AG_ * D_, (long)AG_ * D_,
            1.0f);
    }

    // 4) fused stage 2 -> ATTN (b, n, c)
    {
        dim3 grid(N_ / 32, B_ * H_, 1);
        stage2_kernel<<<grid, 256>>>(qkv, ag, av, attn);
    }

    // 5) depthwise conv residual add into ATTN
    {
        long total = (long)B_ * N_ * C_;
        dwconv_kernel<<<(unsigned)((total + 255) / 256), 256>>>(qkv, dwc_w, dwc_b, attn);
    }

    // 6) out = ATTN @ proj_w^T + proj_b  (mma bf16 3-pass, pipelined)
    {
        dim3 grid(C_ / 128, M / 128, 1);
        mma_gemm<true><<<grid, 256, SM_TOT>>>(attn, proj_w, out, proj_b,
            M, C_, C_, C_, C_, C_,
            0, 0, 0, 0, 0, 0, 1.0f);
    }
}